// round 1
// baseline (speedup 1.0000x reference)
#include <cuda_runtime.h>
#include <math.h>

// ---------------- device scratch (no allocation allowed) ----------------
static __device__ int   g_ntext;
static __device__ int   g_list[8192];
static __device__ float g_ebuf[8192 * 200];

// ---------------- kernel 0: zero the partition counter ----------------
__global__ void kzero() { g_ntext = 0; }

// ---------------- kernel 1: partition batch into text-indexed list ----------------
__global__ void kpart(const int* __restrict__ indices, int B, int NUv)
{
    int i = blockIdx.x * blockDim.x + threadIdx.x;
    if (i < B && indices[i] >= NUv) {
        int p = atomicAdd(&g_ntext, 1);
        g_list[p] = i;
    }
}

// ---------------- kernel 2: text base projection (gathered GEMM) ----------------
// e[b, 0:200] = text_features[indices[b]-NU, 0:768] @ textT[768, 200]
// Block tile: 16 batch rows x 200 cols. 128 threads; threads 0..99 own 2 cols each.
__global__ __launch_bounds__(128) void kgemm(const int* __restrict__ indices,
                                             const float* __restrict__ text_features,
                                             const float* __restrict__ textT,
                                             int NUv)
{
    const int ntext = g_ntext;
    const int base  = blockIdx.x * 16;
    if (base >= ntext) return;
    const int nb  = min(16, ntext - base);
    const int tid = threadIdx.x;

    __shared__ float Xs[16][66];   // [bi][kk], pad 66 so float2 reads stay 8B aligned
    __shared__ int   bls[16];
    __shared__ int   rowss[16];

    if (tid < 16) {
        int bb = g_list[base + (tid < nb ? tid : 0)];
        bls[tid]   = bb;
        rowss[tid] = indices[bb] - NUv;
    }
    __syncthreads();

    float acc[16][2];
#pragma unroll
    for (int i = 0; i < 16; ++i) { acc[i][0] = 0.f; acc[i][1] = 0.f; }

    const bool act = (tid < 100);
    const int  j0  = 2 * tid;

    for (int k0 = 0; k0 < 768; k0 += 64) {
        // cooperative load of X tile: 16 rows x 64 cols, coalesced per row
#pragma unroll
        for (int e = 0; e < 8; ++e) {
            int f  = tid + 128 * e;       // 0..1023
            int bi = f >> 6;
            int kk = f & 63;
            Xs[bi][kk] = text_features[(size_t)rowss[bi] * 768 + k0 + kk];
        }
        __syncthreads();
        if (act) {
            for (int kk = 0; kk < 64; kk += 2) {
                float2 t0 = *(const float2*)(textT + (size_t)(k0 + kk) * 200 + j0);
                float2 t1 = *(const float2*)(textT + (size_t)(k0 + kk + 1) * 200 + j0);
#pragma unroll
                for (int bi = 0; bi < 16; ++bi) {
                    float2 x2 = *(const float2*)&Xs[bi][kk];   // broadcast LDS.64
                    acc[bi][0] = fmaf(x2.x, t0.x, acc[bi][0]);
                    acc[bi][1] = fmaf(x2.x, t0.y, acc[bi][1]);
                    acc[bi][0] = fmaf(x2.y, t1.x, acc[bi][0]);
                    acc[bi][1] = fmaf(x2.y, t1.y, acc[bi][1]);
                }
            }
        }
        __syncthreads();
    }

    if (act) {
        for (int bi = 0; bi < nb; ++bi) {
            float* d = g_ebuf + (size_t)bls[bi] * 200 + j0;
            d[0] = acc[bi][0];
            d[1] = acc[bi][1];
        }
    }
}

// ---------------- kernel 3: fused main (one block per batch element) ----------------
// neighbor-sum -> type matvec -> attention -> base + correction -> L2 normalize
__global__ __launch_bounds__(256) void kmain(
    const int*   __restrict__ train_types,
    const int*   __restrict__ node_neigh,
    const int*   __restrict__ indices,
    const float* __restrict__ user_features,
    const float* __restrict__ neigh,
    const float* __restrict__ tweetW,   // [2,768,20]
    const float* __restrict__ userW,    // [2,32,20]
    const float* __restrict__ TW,       // [2,20,200]
    const float* __restrict__ S1,       // [2,20,20]
    const float* __restrict__ S2,       // [2,20,1]
    const float* __restrict__ userT,    // [32,200]
    float*       __restrict__ out,
    int NUv)
{
    const int  b    = blockIdx.x;
    const int  tid  = threadIdx.x;
    const int  tau  = train_types[b];
    const bool tw   = (tau == 1);
    const int  K    = tw ? 768 : 32;

    __shared__ float  xs[2][768];
    __shared__ float4 part[24][10];
    __shared__ float  nte[2][20];
    __shared__ float  sc[40];
    __shared__ float  att2[2];
    __shared__ float  vsh[20];
    __shared__ float  red[8];
    __shared__ float  s_inv;

    // ---- Phase 1: sum 10 neighbor rows per type slot (only needed K dims) ----
    const int chunks = K >> 2;
#pragma unroll
    for (int t = 0; t < 2; ++t) {
        int rows[10];
#pragma unroll
        for (int s = 0; s < 10; ++s) rows[s] = node_neigh[b * 20 + t * 10 + s];
        for (int c = tid; c < chunks; c += 256) {
            float4 a = make_float4(0.f, 0.f, 0.f, 0.f);
#pragma unroll
            for (int s = 0; s < 10; ++s) {
                float4 v = __ldg((const float4*)(neigh + (size_t)rows[s] * 768 + 4 * c));
                a.x += v.x; a.y += v.y; a.z += v.z; a.w += v.w;
            }
            *(float4*)&xs[t][4 * c] = a;
        }
    }
    __syncthreads();

    // ---- Phase 2: nte[t][u] = xs[t] . W[tau][t][:,u]  (240 threads, 24 k-partials) ----
    if (tid < 240) {
        const int kl   = tid / 10;           // 0..23 k-partition
        const int slot = tid % 10;           // t*5 + u-group
        const int t    = slot / 5;
        const int u0   = (slot % 5) * 4;
        const float* Wb = tw ? (tweetW + (size_t)t * 768 * 20)
                             : (userW  + (size_t)t * 32 * 20);
        float a0 = 0.f, a1 = 0.f, a2 = 0.f, a3 = 0.f;
        for (int k = kl; k < K; k += 24) {
            float  x = xs[t][k];
            float4 w = __ldg((const float4*)(Wb + k * 20 + u0));
            a0 = fmaf(x, w.x, a0); a1 = fmaf(x, w.y, a1);
            a2 = fmaf(x, w.z, a2); a3 = fmaf(x, w.w, a3);
        }
        part[kl][slot] = make_float4(a0, a1, a2, a3);
    }
    __syncthreads();
    if (tid < 40) {
        const int t = tid / 20, u = tid % 20;
        const float* p = (const float*)&part[0][t * 5 + (u >> 2)] + (u & 3);
        float s = 0.f;
#pragma unroll
        for (int k2 = 0; k2 < 24; ++k2) s += p[k2 * 40];
        nte[t][u] = s;
    }
    __syncthreads();

    // ---- Phase 3: attention over the 2 type slots ----
    if (tid < 40) {
        const int t = tid / 20, a = tid % 20;
        float h = 0.f;
#pragma unroll
        for (int u = 0; u < 20; ++u) h = fmaf(nte[t][u], S1[(tau * 20 + u) * 20 + a], h);
        sc[tid] = tanhf(h) * S2[tau * 20 + a];
    }
    __syncthreads();
    if (tid == 0) {
        float s0 = 0.f, s1v = 0.f;
#pragma unroll
        for (int a = 0; a < 20; ++a) { s0 += sc[a]; s1v += sc[20 + a]; }
        float m  = fmaxf(s0, s1v);
        float e0 = expf(s0 - m), e1 = expf(s1v - m);
        float iv = 1.f / (e0 + e1);
        att2[0] = e0 * iv; att2[1] = e1 * iv;
    }
    __syncthreads();
    if (tid < 20) vsh[tid] = att2[0] * nte[0][tid] + att2[1] * nte[1][tid];
    __syncthreads();

    // ---- Phase 4: base embed + correction + L2 normalize ----
    const int idx = indices[b];
    float o = 0.f;
    if (tid < 200) {
        if (idx >= NUv) {
            o = g_ebuf[(size_t)b * 200 + tid];
        } else {
            const float* uf = user_features + (size_t)idx * 32;
#pragma unroll
            for (int k = 0; k < 32; ++k) o = fmaf(uf[k], userT[k * 200 + tid], o);
        }
#pragma unroll
        for (int u = 0; u < 20; ++u) o = fmaf(vsh[u], TW[(tau * 20 + u) * 200 + tid], o);
    }
    float sq = o * o;
#pragma unroll
    for (int off = 16; off; off >>= 1) sq += __shfl_down_sync(0xffffffffu, sq, off);
    if ((tid & 31) == 0) red[tid >> 5] = sq;
    __syncthreads();
    if (tid == 0) {
        float s = 0.f;
#pragma unroll
        for (int w = 0; w < 8; ++w) s += red[w];
        float n = fmaxf(sqrtf(s), 1e-12f);
        s_inv = 1.f / n;
    }
    __syncthreads();
    if (tid < 200) out[(size_t)b * 200 + tid] = o * s_inv;
}

// ---------------- launch ----------------
extern "C" void kernel_launch(void* const* d_in, const int* in_sizes, int n_in,
                              void* d_out, int out_size)
{
    const int*   train_types    = (const int*)  d_in[1];
    const int*   node_neigh     = (const int*)  d_in[2];
    const int*   indices        = (const int*)  d_in[3];
    const float* user_features  = (const float*)d_in[4];
    const float* text_features  = (const float*)d_in[5];
    const float* neigh_features = (const float*)d_in[6];
    const float* textT          = (const float*)d_in[7];
    const float* userT          = (const float*)d_in[8];
    const float* tweetW         = (const float*)d_in[9];
    const float* userW          = (const float*)d_in[10];
    const float* TW             = (const float*)d_in[11];
    const float* S1             = (const float*)d_in[12];
    const float* S2             = (const float*)d_in[13];
    float*       out            = (float*)d_out;

    const int B   = in_sizes[1];          // 4096
    const int NUv = in_sizes[4] / 32;     // 50000

    kzero<<<1, 1>>>();
    kpart<<<(B + 255) / 256, 256>>>(indices, B, NUv);
    kgemm<<<(B + 15) / 16, 128>>>(indices, text_features, textT, NUv);
    kmain<<<B, 256>>>(train_types, node_neigh, indices, user_features, neigh_features,
                      tweetW, userW, TW, S1, S2, userT, out, NUv);
}

// round 2
// speedup vs baseline: 1.2520x; 1.2520x over previous
#include <cuda_runtime.h>
#include <math.h>

// ---------------- device scratch (no allocation allowed) ----------------
static __device__ int   g_ntext;
static __device__ int   g_list[8192];
static __device__ float g_ebuf[8192 * 200];
static __device__ float g_wT[2 * 20 * 768];   // tweet_u_embed_trans transposed [t][u][k]
static __device__ float g_wU[2 * 20 * 32];    // user_u_embed_trans  transposed [t][u][k]

// ---------------- kernel 0: prep (zero counter + transpose type weights) ----------
__global__ __launch_bounds__(256) void kprep(const float* __restrict__ tweetW,
                                             const float* __restrict__ userW)
{
    const int tid = threadIdx.x;
    if (tid == 0) g_ntext = 0;
    // tweetW [t][k][u] (2,768,20) -> g_wT [t][u][k]
    for (int o = tid; o < 2 * 20 * 768; o += 256) {
        int k = o % 768, u = (o / 768) % 20, t = o / (768 * 20);
        g_wT[o] = tweetW[(t * 768 + k) * 20 + u];
    }
    // userW [t][k][u] (2,32,20) -> g_wU [t][u][k]
    for (int o = tid; o < 2 * 20 * 32; o += 256) {
        int k = o % 32, u = (o / 32) % 20, t = o / (32 * 20);
        g_wU[o] = userW[(t * 32 + k) * 20 + u];
    }
}

// ---------------- kernel 1: partition batch into text-indexed list ----------------
__global__ void kpart(const int* __restrict__ indices, int B, int NUv)
{
    int i = blockIdx.x * blockDim.x + threadIdx.x;
    if (i < B && indices[i] >= NUv) {
        int p = atomicAdd(&g_ntext, 1);
        g_list[p] = i;
    }
}

// ---------------- kernel 2: text base projection (gathered GEMM) ----------------
// e[b, 0:200] = text_features[indices[b]-NU, :] @ textT[768, 200]
// Tile: 8 batch rows x 200 cols, 128 threads (100 active, 2 cols each).
// Double-buffered X tile; 512 blocks for latency hiding.
__global__ __launch_bounds__(128) void kgemm(const int* __restrict__ indices,
                                             const float* __restrict__ text_features,
                                             const float* __restrict__ textT,
                                             int NUv)
{
    const int ntext = g_ntext;
    const int base  = blockIdx.x * 8;
    if (base >= ntext) return;
    const int nb  = min(8, ntext - base);
    const int tid = threadIdx.x;

    __shared__ __align__(16) float Xs[2][8][68];   // pad 68: float4-aligned rows
    __shared__ int bls[8];
    __shared__ int rws[8];

    if (tid < 8) {
        int bb = g_list[base + min(tid, nb - 1)];
        bls[tid] = bb;
        rws[tid] = indices[bb] - NUv;
    }
    __syncthreads();

    // cooperative tile load: 8 rows x 64 cols = 128 float4, one per thread
    const int lbi = tid >> 4;
    const int lkk = (tid & 15) << 2;

    *(float4*)&Xs[0][lbi][lkk] =
        *(const float4*)(text_features + (size_t)rws[lbi] * 768 + lkk);
    __syncthreads();

    float acc[8][2];
#pragma unroll
    for (int i = 0; i < 8; ++i) { acc[i][0] = 0.f; acc[i][1] = 0.f; }

    const bool act = (tid < 100);
    const int  j0  = 2 * tid;

    for (int tile = 0; tile < 12; ++tile) {
        const int k0  = tile * 64;
        const int cur = tile & 1;
        if (tile < 11) {
            *(float4*)&Xs[cur ^ 1][lbi][lkk] =
                *(const float4*)(text_features + (size_t)rws[lbi] * 768 + k0 + 64 + lkk);
        }
        if (act) {
#pragma unroll 4
            for (int kk = 0; kk < 64; kk += 2) {
                float2 t0 = __ldg((const float2*)(textT + (size_t)(k0 + kk) * 200 + j0));
                float2 t1 = __ldg((const float2*)(textT + (size_t)(k0 + kk + 1) * 200 + j0));
#pragma unroll
                for (int bi = 0; bi < 8; ++bi) {
                    float2 x2 = *(const float2*)&Xs[cur][bi][kk];
                    acc[bi][0] = fmaf(x2.x, t0.x, acc[bi][0]);
                    acc[bi][1] = fmaf(x2.x, t0.y, acc[bi][1]);
                    acc[bi][0] = fmaf(x2.y, t1.x, acc[bi][0]);
                    acc[bi][1] = fmaf(x2.y, t1.y, acc[bi][1]);
                }
            }
        }
        __syncthreads();
    }

    if (act) {
        for (int bi = 0; bi < nb; ++bi) {
            float* d = g_ebuf + (size_t)bls[bi] * 200 + j0;
            d[0] = acc[bi][0];
            d[1] = acc[bi][1];
        }
    }
}

// ---------------- kernel 3: fused main (one block per batch element) ----------------
__global__ __launch_bounds__(256) void kmain(
    const int*   __restrict__ train_types,
    const int*   __restrict__ node_neigh,
    const int*   __restrict__ indices,
    const float* __restrict__ user_features,
    const float* __restrict__ neigh,
    const float* __restrict__ TW,       // [2,20,200]
    const float* __restrict__ S1,       // [2,20,20]
    const float* __restrict__ S2,       // [2,20,1]
    const float* __restrict__ userT,    // [32,200]
    float*       __restrict__ out,
    int NUv)
{
    const int  b    = blockIdx.x;
    const int  tid  = threadIdx.x;
    const int  lane = tid & 31;
    const int  wid  = tid >> 5;
    const int  tau  = train_types[b];
    const bool tw   = (tau == 1);
    const int  K    = tw ? 768 : 32;

    __shared__ __align__(16) float xs[2][768];
    __shared__ int   rows_s[20];
    __shared__ float nte[2][20];
    __shared__ float sc[40];
    __shared__ float att2[2];
    __shared__ float vsh[20];
    __shared__ float red[8];
    __shared__ float s_inv;

    if (tid < 20) rows_s[tid] = node_neigh[b * 20 + tid];
    __syncthreads();

    // ---- Phase 1: sum 10 neighbor rows per type slot (only needed K dims) ----
    const int cpt   = K >> 2;          // chunks per type slot (192 or 8)
    const int total = 2 * cpt;
    for (int c = tid; c < total; c += 256) {
        const int t  = (c >= cpt) ? 1 : 0;
        const int cc = c - t * cpt;
        const int* rw = rows_s + t * 10;
        float4 a = make_float4(0.f, 0.f, 0.f, 0.f);
#pragma unroll
        for (int s = 0; s < 10; ++s) {
            float4 v = __ldg((const float4*)(neigh + (size_t)rw[s] * 768 + 4 * cc));
            a.x += v.x; a.y += v.y; a.z += v.z; a.w += v.w;
        }
        *(float4*)&xs[t][4 * cc] = a;
    }
    __syncthreads();

    // ---- Phase 2: nte[t][u] = xs[t] . WT[tau][t][u][:]  (warp per task, 5 tasks/warp) ----
    {
        const int nf = K >> 2;
#pragma unroll
        for (int i = 0; i < 5; ++i) {
            const int q = wid * 5 + i;       // 0..39
            const int t = q / 20, u = q % 20;
            const float4* Wq = tw
                ? (const float4*)(g_wT + ((size_t)(t * 20 + u)) * 768)
                : (const float4*)(g_wU + ((size_t)(t * 20 + u)) * 32);
            const float4* Xq = (const float4*)xs[t];
            float a = 0.f;
            for (int f = lane; f < nf; f += 32) {
                float4 w = __ldg(Wq + f);
                float4 x = Xq[f];
                a = fmaf(x.x, w.x, fmaf(x.y, w.y, fmaf(x.z, w.z, fmaf(x.w, w.w, a))));
            }
#pragma unroll
            for (int off = 16; off; off >>= 1) a += __shfl_xor_sync(0xffffffffu, a, off);
            if (lane == 0) nte[t][u] = a;
        }
    }
    __syncthreads();

    // ---- Phase 3: attention over the 2 type slots ----
    if (tid < 40) {
        const int t = tid / 20, a = tid % 20;
        float h = 0.f;
#pragma unroll
        for (int u = 0; u < 20; ++u) h = fmaf(nte[t][u], S1[(tau * 20 + u) * 20 + a], h);
        sc[tid] = tanhf(h) * S2[tau * 20 + a];
    }
    __syncthreads();
    if (tid == 0) {
        float s0 = 0.f, s1v = 0.f;
#pragma unroll
        for (int a = 0; a < 20; ++a) { s0 += sc[a]; s1v += sc[20 + a]; }
        float m  = fmaxf(s0, s1v);
        float e0 = expf(s0 - m), e1 = expf(s1v - m);
        float iv = 1.f / (e0 + e1);
        att2[0] = e0 * iv; att2[1] = e1 * iv;
    }
    __syncthreads();
    if (tid < 20) vsh[tid] = att2[0] * nte[0][tid] + att2[1] * nte[1][tid];
    __syncthreads();

    // ---- Phase 4: base embed + correction + L2 normalize ----
    const int idx = indices[b];
    float o = 0.f;
    if (tid < 200) {
        if (idx >= NUv) {
            o = g_ebuf[(size_t)b * 200 + tid];
        } else {
            const float* uf = user_features + (size_t)idx * 32;
#pragma unroll
            for (int k = 0; k < 32; ++k) o = fmaf(uf[k], userT[k * 200 + tid], o);
        }
#pragma unroll
        for (int u = 0; u < 20; ++u) o = fmaf(vsh[u], TW[(tau * 20 + u) * 200 + tid], o);
    }
    float sq = o * o;
#pragma unroll
    for (int off = 16; off; off >>= 1) sq += __shfl_down_sync(0xffffffffu, sq, off);
    if (lane == 0) red[wid] = sq;
    __syncthreads();
    if (tid == 0) {
        float s = 0.f;
#pragma unroll
        for (int w = 0; w < 8; ++w) s += red[w];
        s_inv = 1.f / fmaxf(sqrtf(s), 1e-12f);
    }
    __syncthreads();
    if (tid < 200) out[(size_t)b * 200 + tid] = o * s_inv;
}

// ---------------- launch ----------------
extern "C" void kernel_launch(void* const* d_in, const int* in_sizes, int n_in,
                              void* d_out, int out_size)
{
    const int*   train_types    = (const int*)  d_in[1];
    const int*   node_neigh     = (const int*)  d_in[2];
    const int*   indices        = (const int*)  d_in[3];
    const float* user_features  = (const float*)d_in[4];
    const float* text_features  = (const float*)d_in[5];
    const float* neigh_features = (const float*)d_in[6];
    const float* textT          = (const float*)d_in[7];
    const float* userT          = (const float*)d_in[8];
    const float* tweetW         = (const float*)d_in[9];
    const float* userW          = (const float*)d_in[10];
    const float* TW             = (const float*)d_in[11];
    const float* S1             = (const float*)d_in[12];
    const float* S2             = (const float*)d_in[13];
    float*       out            = (float*)d_out;

    const int B   = in_sizes[1];          // 4096
    const int NUv = in_sizes[4] / 32;     // 50000

    kprep<<<1, 256>>>(tweetW, userW);
    kpart<<<(B + 255) / 256, 256>>>(indices, B, NUv);
    kgemm<<<(B + 7) / 8, 128>>>(indices, text_features, textT, NUv);
    kmain<<<B, 256>>>(train_types, node_neigh, indices, user_features, neigh_features,
                      TW, S1, S2, userT, out, NUv);
}

// round 3
// speedup vs baseline: 1.7847x; 1.4255x over previous
#include <cuda_runtime.h>
#include <math.h>

// ---------------- device scratch (no allocation allowed) ----------------
static __device__ int   g_ntext;
static __device__ int   g_list[8192];
static __device__ float g_ebuf[8192 * 200];

// ---------------- kernel 0: zero partition counter ----------------
__global__ void kzero() { g_ntext = 0; }

// ---------------- kernel 1: partition batch into text-indexed list ----------------
__global__ void kpart(const int* __restrict__ indices, int B, int NUv)
{
    int i = blockIdx.x * blockDim.x + threadIdx.x;
    if (i < B && indices[i] >= NUv) {
        int p = atomicAdd(&g_ntext, 1);
        g_list[p] = i;
    }
}

// ---------------- kernel 2: text base projection (gathered GEMM) ----------------
// e[b, :] = text_features[indices[b]-NU, :] @ textT[768, 200]
// Tile: 16 batch rows x 200 cols. 256 threads = two 128-thread halves, each
// half owns 8 rows; threads 0..99 of each half own 2 cols. k-quad inner loop.
__global__ __launch_bounds__(256) void kgemm(const int* __restrict__ indices,
                                             const float* __restrict__ text_features,
                                             const float* __restrict__ textT,
                                             int NUv)
{
    const int ntext = g_ntext;
    const int base  = blockIdx.x * 16;
    if (base >= ntext) return;
    const int tid  = threadIdx.x;
    const int half = tid >> 7;       // 0 or 1
    const int ht   = tid & 127;

    __shared__ __align__(16) float Xs[2][16][68];  // 68-f pad: float4 rows, no conflicts
    __shared__ int bls[16];
    __shared__ int rws[16];

    if (tid < 16) {
        int p   = base + tid;
        int src = min(p, ntext - 1);
        int bb  = g_list[src];
        bls[tid] = (p < ntext) ? bb : -1;
        rws[tid] = indices[bb] - NUv;
    }
    __syncthreads();

    const int lbi = tid >> 4;
    const int lkk = (tid & 15) << 2;
    const float* xrow = text_features + (size_t)rws[lbi] * 768;

    *(float4*)&Xs[0][lbi][lkk] = *(const float4*)(xrow + lkk);
    __syncthreads();

    float acc[8][2];
#pragma unroll
    for (int i = 0; i < 8; ++i) { acc[i][0] = 0.f; acc[i][1] = 0.f; }

    const bool act = (ht < 100);
    const int  j0  = 2 * ht;
    const int  r0  = half * 8;

    for (int tile = 0; tile < 12; ++tile) {
        const int k0  = tile * 64;
        const int cur = tile & 1;
        if (tile < 11)
            *(float4*)&Xs[cur ^ 1][lbi][lkk] = *(const float4*)(xrow + k0 + 64 + lkk);
        if (act) {
#pragma unroll
            for (int kk = 0; kk < 64; kk += 4) {
                float2 w0 = __ldg((const float2*)(textT + (size_t)(k0 + kk    ) * 200 + j0));
                float2 w1 = __ldg((const float2*)(textT + (size_t)(k0 + kk + 1) * 200 + j0));
                float2 w2 = __ldg((const float2*)(textT + (size_t)(k0 + kk + 2) * 200 + j0));
                float2 w3 = __ldg((const float2*)(textT + (size_t)(k0 + kk + 3) * 200 + j0));
#pragma unroll
                for (int bi = 0; bi < 8; ++bi) {
                    float4 x = *(const float4*)&Xs[cur][r0 + bi][kk];
                    acc[bi][0] = fmaf(x.x, w0.x, acc[bi][0]);
                    acc[bi][1] = fmaf(x.x, w0.y, acc[bi][1]);
                    acc[bi][0] = fmaf(x.y, w1.x, acc[bi][0]);
                    acc[bi][1] = fmaf(x.y, w1.y, acc[bi][1]);
                    acc[bi][0] = fmaf(x.z, w2.x, acc[bi][0]);
                    acc[bi][1] = fmaf(x.z, w2.y, acc[bi][1]);
                    acc[bi][0] = fmaf(x.w, w3.x, acc[bi][0]);
                    acc[bi][1] = fmaf(x.w, w3.y, acc[bi][1]);
                }
            }
        }
        __syncthreads();
    }

    if (act) {
#pragma unroll
        for (int bi = 0; bi < 8; ++bi) {
            int bb = bls[r0 + bi];
            if (bb >= 0) {
                float* d = g_ebuf + (size_t)bb * 200 + j0;
                d[0] = acc[bi][0];
                d[1] = acc[bi][1];
            }
        }
    }
}

// ---------------- kernel 3: fused main (one block per batch element) ----------------
__global__ __launch_bounds__(256) void kmain(
    const int*   __restrict__ train_types,
    const int*   __restrict__ node_neigh,
    const int*   __restrict__ indices,
    const float* __restrict__ user_features,
    const float* __restrict__ neigh,
    const float* __restrict__ tweetW,   // [2,768,20]
    const float* __restrict__ userW,    // [2,32,20]
    const float* __restrict__ TW,       // [2,20,200]
    const float* __restrict__ S1,       // [2,20,20]
    const float* __restrict__ S2,       // [2,20,1]
    const float* __restrict__ userT,    // [32,200]
    float*       __restrict__ out,
    int NUv)
{
    const int  b    = blockIdx.x;
    const int  tid  = threadIdx.x;
    const int  lane = tid & 31;
    const int  wid  = tid >> 5;
    const int  tau  = train_types[b];
    const bool tw   = (tau == 1);
    const int  K    = tw ? 768 : 32;

    __shared__ __align__(16) float xs[2][768];
    __shared__ int    rows_s[20];
    __shared__ float4 part[24][10];
    __shared__ float  nte[2][20];
    __shared__ float  sc[40];
    __shared__ float  att2[2];
    __shared__ float  vsh[20];
    __shared__ float  red[8];
    __shared__ float  s_inv;

    if (tid < 20) rows_s[tid] = node_neigh[b * 20 + tid];
    __syncthreads();

    // ---- Phase 1: sum 10 neighbor rows per type slot (only needed K dims) ----
    if (tw) {
        // 384 chunks total (192 per slot). Pass A: c = tid (all 256).
        {
            const int c  = tid;
            const int t  = (c >= 192) ? 1 : 0;
            const int cc = c - t * 192;
            const int* rw = rows_s + t * 10;
            float4 a = make_float4(0.f, 0.f, 0.f, 0.f);
#pragma unroll
            for (int s = 0; s < 10; ++s) {
                float4 v = __ldg((const float4*)(neigh + (size_t)rw[s] * 768 + 4 * cc));
                a.x += v.x; a.y += v.y; a.z += v.z; a.w += v.w;
            }
            *(float4*)&xs[t][4 * cc] = a;
        }
        // Pass B: c = 256 + tid (tid < 128) -> slot 1, cc = tid + 64.
        if (tid < 128) {
            const int cc = tid + 64;
            const int* rw = rows_s + 10;
            float4 a = make_float4(0.f, 0.f, 0.f, 0.f);
#pragma unroll
            for (int s = 0; s < 10; ++s) {
                float4 v = __ldg((const float4*)(neigh + (size_t)rw[s] * 768 + 4 * cc));
                a.x += v.x; a.y += v.y; a.z += v.z; a.w += v.w;
            }
            *(float4*)&xs[1][4 * cc] = a;
        }
    } else {
        if (tid < 16) {
            const int t  = tid >> 3;
            const int cc = tid & 7;
            const int* rw = rows_s + t * 10;
            float4 a = make_float4(0.f, 0.f, 0.f, 0.f);
#pragma unroll
            for (int s = 0; s < 10; ++s) {
                float4 v = __ldg((const float4*)(neigh + (size_t)rw[s] * 768 + 4 * cc));
                a.x += v.x; a.y += v.y; a.z += v.z; a.w += v.w;
            }
            *(float4*)&xs[t][4 * cc] = a;
        }
    }
    __syncthreads();

    // ---- Phase 2: nte[t][u] = xs[t] . W[tau][t][:,u]  (240 threads, 24 k-partials) ----
    if (tid < 240) {
        const int kl   = tid / 10;           // 0..23
        const int slot = tid % 10;           // t*5 + u-quad
        const int t    = slot / 5;
        const int u0   = (slot % 5) * 4;
        const float* Wb = tw ? (tweetW + (size_t)t * 768 * 20)
                             : (userW  + (size_t)t * 32 * 20);
        float a0 = 0.f, a1 = 0.f, a2 = 0.f, a3 = 0.f;
        for (int k = kl; k < K; k += 24) {
            float  x = xs[t][k];
            float4 w = __ldg((const float4*)(Wb + k * 20 + u0));
            a0 = fmaf(x, w.x, a0); a1 = fmaf(x, w.y, a1);
            a2 = fmaf(x, w.z, a2); a3 = fmaf(x, w.w, a3);
        }
        part[kl][slot] = make_float4(a0, a1, a2, a3);
    }
    __syncthreads();
    if (tid < 40) {
        const int t = tid / 20, u = tid % 20;
        const float* p = (const float*)&part[0][t * 5 + (u >> 2)] + (u & 3);
        float s = 0.f;
#pragma unroll
        for (int k2 = 0; k2 < 24; ++k2) s += p[k2 * 40];
        nte[t][u] = s;
    }
    __syncthreads();

    // ---- Phase 3: attention over the 2 type slots ----
    if (tid < 40) {
        const int t = tid / 20, a = tid % 20;
        float h = 0.f;
#pragma unroll
        for (int u = 0; u < 20; ++u) h = fmaf(nte[t][u], S1[(tau * 20 + u) * 20 + a], h);
        sc[tid] = tanhf(h) * S2[tau * 20 + a];
    }
    __syncthreads();
    if (tid == 0) {
        float s0 = 0.f, s1v = 0.f;
#pragma unroll
        for (int a = 0; a < 20; ++a) { s0 += sc[a]; s1v += sc[20 + a]; }
        float m  = fmaxf(s0, s1v);
        float e0 = expf(s0 - m), e1 = expf(s1v - m);
        float iv = 1.f / (e0 + e1);
        att2[0] = e0 * iv; att2[1] = e1 * iv;
    }
    __syncthreads();
    if (tid < 20) vsh[tid] = att2[0] * nte[0][tid] + att2[1] * nte[1][tid];
    __syncthreads();

    // ---- Phase 4: base embed + correction + L2 normalize ----
    const int idx = indices[b];
    float o = 0.f;
    if (tid < 200) {
        if (idx >= NUv) {
            o = g_ebuf[(size_t)b * 200 + tid];
        } else {
            const float* uf = user_features + (size_t)idx * 32;
#pragma unroll
            for (int k = 0; k < 32; ++k) o = fmaf(uf[k], userT[k * 200 + tid], o);
        }
#pragma unroll
        for (int u = 0; u < 20; ++u) o = fmaf(vsh[u], TW[(tau * 20 + u) * 200 + tid], o);
    }
    float sq = o * o;
#pragma unroll
    for (int off = 16; off; off >>= 1) sq += __shfl_down_sync(0xffffffffu, sq, off);
    if (lane == 0) red[wid] = sq;
    __syncthreads();
    if (tid == 0) {
        float s = 0.f;
#pragma unroll
        for (int w = 0; w < 8; ++w) s += red[w];
        s_inv = 1.f / fmaxf(sqrtf(s), 1e-12f);
    }
    __syncthreads();
    if (tid < 200) out[(size_t)b * 200 + tid] = o * s_inv;
}

// ---------------- launch ----------------
extern "C" void kernel_launch(void* const* d_in, const int* in_sizes, int n_in,
                              void* d_out, int out_size)
{
    const int*   train_types    = (const int*)  d_in[1];
    const int*   node_neigh     = (const int*)  d_in[2];
    const int*   indices        = (const int*)  d_in[3];
    const float* user_features  = (const float*)d_in[4];
    const float* text_features  = (const float*)d_in[5];
    const float* neigh_features = (const float*)d_in[6];
    const float* textT          = (const float*)d_in[7];
    const float* userT          = (const float*)d_in[8];
    const float* tweetW         = (const float*)d_in[9];
    const float* userW          = (const float*)d_in[10];
    const float* TW             = (const float*)d_in[11];
    const float* S1             = (const float*)d_in[12];
    const float* S2             = (const float*)d_in[13];
    float*       out            = (float*)d_out;

    const int B   = in_sizes[1];          // 4096
    const int NUv = in_sizes[4] / 32;     // 50000

    kzero<<<1, 1>>>();
    kpart<<<(B + 255) / 256, 256>>>(indices, B, NUv);
    kgemm<<<(B + 15) / 16, 256>>>(indices, text_features, textT, NUv);
    kmain<<<B, 256>>>(train_types, node_neigh, indices, user_features, neigh_features,
                      tweetW, userW, TW, S1, S2, userT, out, NUv);
}